// round 16
// baseline (speedup 1.0000x reference)
#include <cuda_runtime.h>
#include <cuda_fp16.h>
#include <cstdint>

#define BB 4
#define TT 2048
#define CC 576
#define HH 12
#define DD 48
#define MM (BB*TT)       /* 8192 */
#define NQKV (3*CC)      /* 1728 */

// Scratch (device globals, declared as uint4 for 16B alignment; allocation-free)
__device__ uint4 g_q4 [BB*HH*TT*DD/8];   // q half [b,h,t,d], pre-scaled log2e/sqrt(48)
__device__ uint4 g_k4 [BB*HH*TT*DD/8];   // k half [b,h,t,d]
__device__ uint4 g_v4 [BB*HH*TT*DD/8];   // v half [b,h,t,d] row-major
__device__ uint4 g_y4 [BB*TT*CC/8];      // attention output, half [b,t,c]
__device__ uint4 g_xh4[MM*CC/8];         // x rounded to half
__device__ uint4 g_wqh4[NQKV*CC/8];      // w_qkv half
__device__ uint4 g_wph4[CC*CC/8];        // w_proj half
#define g_q  ((__half*)g_q4)
#define g_k  ((__half*)g_k4)
#define g_v  ((__half*)g_v4)
#define g_y  ((__half*)g_y4)
#define g_xh ((__half*)g_xh4)
#define g_wqh ((__half*)g_wqh4)
#define g_wph ((__half*)g_wph4)

// ---------------------------------------------------------------------------
// helpers
// ---------------------------------------------------------------------------
__device__ __forceinline__ void mma_f16(float c[4],
                                        unsigned a0, unsigned a1, unsigned a2, unsigned a3,
                                        unsigned b0, unsigned b1) {
    asm volatile(
        "mma.sync.aligned.m16n8k16.row.col.f32.f16.f16.f32 "
        "{%0,%1,%2,%3}, {%4,%5,%6,%7}, {%8,%9}, {%0,%1,%2,%3};"
        : "+f"(c[0]), "+f"(c[1]), "+f"(c[2]), "+f"(c[3])
        : "r"(a0), "r"(a1), "r"(a2), "r"(a3), "r"(b0), "r"(b1));
}

__device__ __forceinline__ void ldsm_x4(unsigned &r0, unsigned &r1,
                                        unsigned &r2, unsigned &r3, uint32_t a) {
    asm volatile("ldmatrix.sync.aligned.m8n8.x4.shared.b16 {%0,%1,%2,%3}, [%4];"
                 : "=r"(r0), "=r"(r1), "=r"(r2), "=r"(r3) : "r"(a));
}

__device__ __forceinline__ void ldsm_x4t(unsigned &r0, unsigned &r1,
                                         unsigned &r2, unsigned &r3, uint32_t a) {
    asm volatile("ldmatrix.sync.aligned.m8n8.x4.trans.shared.b16 {%0,%1,%2,%3}, [%4];"
                 : "=r"(r0), "=r"(r1), "=r"(r2), "=r"(r3) : "r"(a));
}

__device__ __forceinline__ void ldsm_x2t(unsigned &r0, unsigned &r1, uint32_t a) {
    asm volatile("ldmatrix.sync.aligned.m8n8.x2.trans.shared.b16 {%0,%1}, [%2];"
                 : "=r"(r0), "=r"(r1) : "r"(a));
}

__device__ __forceinline__ unsigned ex2h2(float u0, float u1) {
    __half2 h = __floats2half2_rn(u0, u1);
    unsigned r;
    asm("ex2.approx.f16x2 %0, %1;" : "=r"(r) : "r"(*reinterpret_cast<unsigned*>(&h)));
    return r;
}

__device__ __forceinline__ void cp16(uint32_t saddr, const void* gp) {
    asm volatile("cp.async.cg.shared.global [%0], [%1], 16;"
                 :: "r"(saddr), "l"(__cvta_generic_to_global(gp)));
}
__device__ __forceinline__ void cp_commit() {
    asm volatile("cp.async.commit_group;");
}

// ---------------------------------------------------------------------------
// prep: fused fp16 conversion of all three GEMM inputs
// ---------------------------------------------------------------------------
#define N4_X  (MM*CC/4)
#define N4_WQ (NQKV*CC/4)
#define N4_WP (CC*CC/4)
__global__ void round_all(const float* __restrict__ x, const float* __restrict__ wq,
                          const float* __restrict__ wp)
{
    int i = blockIdx.x * blockDim.x + threadIdx.x;
    const float4* src;
    __half2* dst;
    if (i < N4_X) {
        src = (const float4*)x; dst = (__half2*)g_xh;
    } else if (i < N4_X + N4_WQ) {
        i -= N4_X;
        src = (const float4*)wq; dst = (__half2*)g_wqh;
    } else if (i < N4_X + N4_WQ + N4_WP) {
        i -= N4_X + N4_WQ;
        src = (const float4*)wp; dst = (__half2*)g_wph;
    } else return;
    float4 v = src[i];
    dst[2*i]   = __floats2half2_rn(v.x, v.y);
    dst[2*i+1] = __floats2half2_rn(v.z, v.w);
}

// ---------------------------------------------------------------------------
// FP16 tensor-core GEMM (mma.sync): out[m][n] = sum_k A[m][k]*W[n][k], K=576.
// CTA 256x64, 256 threads = 8 warps, warp tile 32x64. BK=64 halves, cp.async
// double-buffered, one barrier per iter, ldmatrix fragment loads.
// scatter!=0: qkv epilogue -> g_q (pre-scaled log2e/sqrt48) / g_k / g_v
// (all row-major [t][d], coalesced half2 stores).
// ---------------------------------------------------------------------------
#define SH 72                       /* smem row stride in halves (64+8) */
#define GA_H (256*SH)
#define GB_H (64*SH)
#define GBUF_H (GA_H + GB_H)
#define GSM_BYTES (2*GBUF_H*2)

extern __shared__ __align__(16) unsigned char sm_raw[];

__global__ __launch_bounds__(256) void gemm_tc(
    const __half* __restrict__ A, const __half* __restrict__ W,
    float* __restrict__ out, int Ndim, int scatter)
{
    __half* sh = (__half*)sm_raw;
    const int tid  = threadIdx.x;
    const int wid  = tid >> 5, lane = tid & 31;
    const int g    = lane >> 2, c = lane & 3;
    const int r8   = lane & 7, quad = lane >> 3;
    const int m0   = blockIdx.y * 256;
    const int n0   = blockIdx.x * 64;
    const uint32_t smbase = (uint32_t)__cvta_generic_to_shared(sh);

    const int aRow = (quad & 1) * 8 + r8;
    const int aCol = (quad >> 1) * 8;
    const int bRow = (quad >> 1) * 8 + r8;
    const int bCol = (quad & 1) * 8;

    float acc[2][8][4];
#pragma unroll
    for (int i = 0; i < 2; i++)
#pragma unroll
        for (int j = 0; j < 8; j++)
#pragma unroll
            for (int e = 0; e < 4; e++) acc[i][j][e] = 0.f;

    auto issue = [&](int it) {
        const int k0 = it * 64;
        const uint32_t base = smbase + (uint32_t)(it & 1) * (GBUF_H * 2);
#pragma unroll
        for (int i = 0; i < 8; i++) {
            const int idx = tid + i * 256;
            const int row = idx >> 3, ch = idx & 7;
            cp16(base + (uint32_t)(row * SH + ch * 8) * 2,
                 A + (size_t)(m0 + row) * 576 + k0 + ch * 8);
        }
        const uint32_t bb = base + GA_H * 2;
#pragma unroll
        for (int i = 0; i < 2; i++) {
            const int idx = tid + i * 256;
            const int row = idx >> 3, ch = idx & 7;
            cp16(bb + (uint32_t)(row * SH + ch * 8) * 2,
                 W + (size_t)(n0 + row) * 576 + k0 + ch * 8);
        }
        cp_commit();
    };

    issue(0);
    for (int it = 0; it < 9; it++) {
        asm volatile("cp.async.wait_group 0;");
        __syncthreads();
        if (it + 1 < 9) issue(it + 1);
        const uint32_t aB = smbase + (uint32_t)(it & 1) * (GBUF_H * 2);
        const uint32_t bB = aB + GA_H * 2;

#pragma unroll
        for (int kk = 0; kk < 4; kk++) {
            unsigned a[2][4];
#pragma unroll
            for (int i = 0; i < 2; i++)
                ldsm_x4(a[i][0], a[i][1], a[i][2], a[i][3],
                        aB + (uint32_t)((wid * 32 + i * 16 + aRow) * SH + kk * 16 + aCol) * 2);
#pragma unroll
            for (int jp = 0; jp < 4; jp++) {
                unsigned b00, b01, b10, b11;
                ldsm_x4(b00, b01, b10, b11,
                        bB + (uint32_t)((jp * 16 + bRow) * SH + kk * 16 + bCol) * 2);
#pragma unroll
                for (int i = 0; i < 2; i++) {
                    mma_f16(acc[i][2 * jp], a[i][0], a[i][1], a[i][2], a[i][3], b00, b01);
                    mma_f16(acc[i][2 * jp + 1], a[i][0], a[i][1], a[i][2], a[i][3], b10, b11);
                }
            }
        }
    }

    // q pre-scale folds softmax's log2e: exp(s/sqrt48) == 2^(s*qscale)
    const float qscale = 0.14433756729740643f * 1.4426950408889634f;
#pragma unroll
    for (int i = 0; i < 2; i++) {
#pragma unroll
        for (int j = 0; j < 8; j++) {
            const int col = n0 + j * 8 + 2 * c;
#pragma unroll
            for (int half_ = 0; half_ < 2; half_++) {
                const int m = m0 + wid * 32 + i * 16 + g + half_ * 8;
                float v0 = acc[i][j][half_ * 2 + 0];
                float v1 = acc[i][j][half_ * 2 + 1];
                if (scatter) {
                    const int b = m >> 11, t = m & 2047;
                    const int which = col / CC;
                    const int cc = col - which * CC;
                    const int h = cc / DD, d = cc - h * DD;
                    const size_t bh = (size_t)b * HH + h;
                    if (which == 0) {
                        *(__half2*)&g_q[(bh * TT + t) * DD + d] =
                            __floats2half2_rn(v0 * qscale, v1 * qscale);
                    } else if (which == 1) {
                        *(__half2*)&g_k[(bh * TT + t) * DD + d] = __floats2half2_rn(v0, v1);
                    } else {
                        *(__half2*)&g_v[(bh * TT + t) * DD + d] = __floats2half2_rn(v0, v1);
                    }
                } else {
                    float2 st; st.x = v0; st.y = v1;
                    *(float2*)&out[(size_t)m * Ndim + col] = st;
                }
            }
        }
    }
}

// ---------------------------------------------------------------------------
// Flash attention, fp16 mma.sync. BR=256, BC=64, 256 threads = 8 warps, each
// warp owns TWO m16 fragments (rows wid*32 + mi*16). Halves K/V L2 traffic
// vs BR=128. Log2-domain softmax (q pre-scaled): P = ex2(S) fused into the
// PV loop; l via static ones-column at d=48 (7th PV mma, ldmatrix.x2.trans).
// Fully-masked diagonal sub-blocks are skipped per-warp (exact: P would be 0).
// K/V double-buffered cp.async; one barrier per iteration.
// ---------------------------------------------------------------------------
#define SMK 56                       /* K row stride halves */
#define SMV 56                       /* V row stride halves: 48 data + 8 static */
#define OFF_K0 0
#define OFF_K1 (64*SMK)
#define OFF_V0 (2*64*SMK)
#define OFF_V1 (2*64*SMK + 64*SMV)
#define ASM_BYTES ((2*64*SMK + 2*64*SMV) * 2)

__global__ __launch_bounds__(256, 1) void attn_tc(__half* __restrict__ ypre)
{
    __half* sh = (__half*)sm_raw;
    const int rb = (gridDim.x - 1) - blockIdx.x;   // heavy blocks first
    const int h = blockIdx.y, b = blockIdx.z;
    const int tid = threadIdx.x, wid = tid >> 5, lane = tid & 31;
    const int g = lane >> 2, c = lane & 3;
    const int r8 = lane & 7, quad = lane >> 3;
    const int bRow = (quad >> 1) * 8 + r8;         // K (non-trans) B-pair offsets
    const int bCol = (quad & 1) * 8;
    const int vRow = (quad & 1) * 8 + r8;          // V (trans) offsets
    const int vCol = (quad >> 1) * 8;
    const int vRow2 = ((lane >> 3) & 1) * 8 + r8;  // x2 trans
    const int t0 = rb * 256;
    const int nblk = 4 * rb + 4;
    const size_t bh = ((size_t)b * HH + h) * TT;   // q,k,v all [t][d]

    // static init: V cols 48..55 of both buffers: col48 = 1.0, 49..55 = 0
    for (int idx = tid; idx < 2 * 64 * 4; idx += 256) {
        const int buf = idx >> 8;
        const int rem = idx & 255;
        const int row = rem >> 2, w = rem & 3;
        ((unsigned*)(sh + (buf ? OFF_V1 : OFF_V0)))[row * (SMV / 2) + 24 + w] =
            (w == 0) ? 0x00003C00u : 0u;
    }

    // Q a-fragments for both m-frags: 3 k16-steps over d=48
    unsigned qa[2][3][4];
#pragma unroll
    for (int mi = 0; mi < 2; mi++) {
        const unsigned* Qw = (const unsigned*)(g_q + (bh + t0 + wid * 32 + mi * 16) * DD);
#pragma unroll
        for (int kk = 0; kk < 3; kk++) {
            qa[mi][kk][0] = Qw[(g) * 24 + kk * 8 + c];
            qa[mi][kk][1] = Qw[(g + 8) * 24 + kk * 8 + c];
            qa[mi][kk][2] = Qw[(g) * 24 + kk * 8 + c + 4];
            qa[mi][kk][3] = Qw[(g + 8) * 24 + kk * 8 + c + 4];
        }
    }

    float o[2][7][4];                // o[mi][6] = l column (d=48 ones col)
#pragma unroll
    for (int mi = 0; mi < 2; mi++)
#pragma unroll
        for (int nf = 0; nf < 7; nf++)
#pragma unroll
            for (int e = 0; e < 4; e++) o[mi][nf][e] = 0.f;

    const uint32_t smbase = (uint32_t)__cvta_generic_to_shared(sh);

    auto issue = [&](int jb) {
        const uint32_t kb = smbase + ((jb & 1) ? OFF_K1 : OFF_K0) * 2;
        const uint32_t vb = smbase + ((jb & 1) ? OFF_V1 : OFF_V0) * 2;
#pragma unroll
        for (int i = 0; i < 2; i++) {
            const int idx = tid + i * 256;
            if (idx < 384) {
                const int row = idx / 6, ch = idx % 6;
                cp16(kb + (uint32_t)(row * SMK + ch * 8) * 2,
                     g_k + (bh + (size_t)jb * 64 + row) * DD + ch * 8);
            }
        }
#pragma unroll
        for (int i = 0; i < 2; i++) {
            const int idx = tid + i * 256;
            if (idx < 384) {
                const int row = idx / 6, ch = idx % 6;
                cp16(vb + (uint32_t)(row * SMV + ch * 8) * 2,
                     g_v + (bh + (size_t)jb * 64 + row) * DD + ch * 8);
            }
        }
        cp_commit();
    };

    issue(0);
    for (int jb = 0; jb < nblk; jb++) {
        asm volatile("cp.async.wait_group 0;");
        __syncthreads();
        if (jb + 1 < nblk) issue(jb + 1);

        // skip warps whose rows are all above (before) this key block: P == 0
        const bool active = !(jb >= 4 * rb && (jb - 4 * rb) * 64 > wid * 32 + 31);
        if (active) {
            const uint32_t kB = smbase + ((jb & 1) ? OFF_K1 : OFF_K0) * 2;
            const uint32_t vB = smbase + ((jb & 1) ? OFF_V1 : OFF_V0) * 2;

            // S = Q K^T (log2 units via q pre-scale); K b-frags shared by mi
            float s[2][8][4];
#pragma unroll
            for (int mi = 0; mi < 2; mi++)
#pragma unroll
                for (int f = 0; f < 8; f++)
#pragma unroll
                    for (int e = 0; e < 4; e++) s[mi][f][e] = 0.f;
#pragma unroll
            for (int kk = 0; kk < 3; kk++) {
#pragma unroll
                for (int fp = 0; fp < 4; fp++) {
                    unsigned b00, b01, b10, b11;
                    ldsm_x4(b00, b01, b10, b11,
                            kB + (uint32_t)((fp * 16 + bRow) * SMK + kk * 16 + bCol) * 2);
#pragma unroll
                    for (int mi = 0; mi < 2; mi++) {
                        mma_f16(s[mi][2 * fp], qa[mi][kk][0], qa[mi][kk][1],
                                qa[mi][kk][2], qa[mi][kk][3], b00, b01);
                        mma_f16(s[mi][2 * fp + 1], qa[mi][kk][0], qa[mi][kk][1],
                                qa[mi][kk][2], qa[mi][kk][3], b10, b11);
                    }
                }
            }

            if (jb >= 4 * rb) {
                const int off = (jb - 4 * rb) * 64;
#pragma unroll
                for (int mi = 0; mi < 2; mi++) {
                    const int ra  = wid * 32 + mi * 16 + g - off;
                    const int ra8 = ra + 8;
#pragma unroll
                    for (int f = 0; f < 8; f++) {
                        const int col = f * 8 + 2 * c;
                        if (col > ra)       s[mi][f][0] = -1e30f;
                        if (col + 1 > ra)   s[mi][f][1] = -1e30f;
                        if (col > ra8)      s[mi][f][2] = -1e30f;
                        if (col + 1 > ra8)  s[mi][f][3] = -1e30f;
                    }
                }
            }

            // O += P V with P = ex2(S) computed in-loop (a-frag layout match).
#pragma unroll
            for (int kk = 0; kk < 4; kk++) {
                unsigned pa[2][4];
#pragma unroll
                for (int mi = 0; mi < 2; mi++) {
                    pa[mi][0] = ex2h2(s[mi][2*kk][0],   s[mi][2*kk][1]);
                    pa[mi][1] = ex2h2(s[mi][2*kk][2],   s[mi][2*kk][3]);
                    pa[mi][2] = ex2h2(s[mi][2*kk+1][0], s[mi][2*kk+1][1]);
                    pa[mi][3] = ex2h2(s[mi][2*kk+1][2], s[mi][2*kk+1][3]);
                }
#pragma unroll
                for (int np = 0; np < 3; np++) {
                    unsigned b00, b01, b10, b11;
                    ldsm_x4t(b00, b01, b10, b11,
                             vB + (uint32_t)((kk * 16 + vRow) * SMV + np * 16 + vCol) * 2);
#pragma unroll
                    for (int mi = 0; mi < 2; mi++) {
                        mma_f16(o[mi][2 * np],     pa[mi][0], pa[mi][1], pa[mi][2], pa[mi][3], b00, b01);
                        mma_f16(o[mi][2 * np + 1], pa[mi][0], pa[mi][1], pa[mi][2], pa[mi][3], b10, b11);
                    }
                }
                {
                    unsigned b0, b1;
                    ldsm_x2t(b0, b1,
                             vB + (uint32_t)((kk * 16 + vRow2) * SMV + 48) * 2);
#pragma unroll
                    for (int mi = 0; mi < 2; mi++)
                        mma_f16(o[mi][6], pa[mi][0], pa[mi][1], pa[mi][2], pa[mi][3], b0, b1);
                }
            }
        }
    }

    // finalize: l lives in o[mi][6] elems 0/2 of lanes c==0 (col 48)
#pragma unroll
    for (int mi = 0; mi < 2; mi++) {
        const float la = __shfl_sync(0xffffffffu, o[mi][6][0], lane & ~3);
        const float lb = __shfl_sync(0xffffffffu, o[mi][6][2], lane & ~3);
        const float ia = 1.f / la, ib = 1.f / lb;
        const int ra = t0 + wid * 32 + mi * 16 + g;
        __half* ya = ypre + ((size_t)b * TT + ra) * CC + h * DD;
        __half* yb = ypre + ((size_t)b * TT + ra + 8) * CC + h * DD;
#pragma unroll
        for (int nf = 0; nf < 6; nf++) {
            const int d = nf * 8 + 2 * c;
            *(__half2*)&ya[d] = __floats2half2_rn(o[mi][nf][0] * ia, o[mi][nf][1] * ia);
            *(__half2*)&yb[d] = __floats2half2_rn(o[mi][nf][2] * ib, o[mi][nf][3] * ib);
        }
    }
}

extern "C" void kernel_launch(void* const* d_in, const int* in_sizes, int n_in,
                              void* d_out, int out_size)
{
    (void)in_sizes; (void)n_in; (void)out_size;
    const float* x      = (const float*)d_in[0];
    const float* w_qkv  = (const float*)d_in[1];
    const float* w_proj = (const float*)d_in[2];
    float* out = (float*)d_out;

    void *yp = nullptr, *xh = nullptr, *wqh = nullptr, *wph = nullptr;
    cudaGetSymbolAddress(&yp,  g_y4);
    cudaGetSymbolAddress(&xh,  g_xh4);
    cudaGetSymbolAddress(&wqh, g_wqh4);
    cudaGetSymbolAddress(&wph, g_wph4);

    cudaFuncSetAttribute(gemm_tc, cudaFuncAttributeMaxDynamicSharedMemorySize, GSM_BYTES);
    cudaFuncSetAttribute(attn_tc, cudaFuncAttributeMaxDynamicSharedMemorySize, ASM_BYTES);

    // 0) convert all GEMM inputs to fp16, fused
    {
        const int total = N4_X + N4_WQ + N4_WP;
        round_all<<<(total + 255) / 256, 256>>>(x, w_qkv, w_proj);
    }
    // 1) qkv GEMM -> scatter q/k/v (row-major, coalesced)
    {
        dim3 grid(NQKV / 64, MM / 256);
        gemm_tc<<<grid, 256, GSM_BYTES>>>((const __half*)xh, (const __half*)wqh,
                                          nullptr, NQKV, 1);
    }
    // 2) causal flash attention (BR=256) -> g_y [B,T,C] (half)
    {
        dim3 grid(TT / 256, HH, BB);
        attn_tc<<<grid, 256, ASM_BYTES>>>((__half*)yp);
    }
    // 3) output projection (fp32 out)
    {
        dim3 grid(CC / 64, MM / 256);
        gemm_tc<<<grid, 256, GSM_BYTES>>>((const __half*)yp, (const __half*)wph,
                                          out, CC, 0);
    }
}